// round 4
// baseline (speedup 1.0000x reference)
#include <cuda_runtime.h>
#include <cstdint>

#define N_ANCH   300000
#define N_CLS    80
#define DET_DIM  85
#define TOPK     1000
#define MAXBOX   300
#define CAP      4096
#define NMS_THR  0.4f

#define GRIDB    148          // <= SM count -> all blocks co-resident -> sw grid barrier safe
#define NTHR     1024
#define APT      256          // anchors per tile in score phase
#define NTILES   ((N_ANCH + APT - 1) / APT)   // 1172
#define SRED_PITCH 21         // 20 float4-maxima per anchor, padded to 21 (bank-conflict free)
#define DYN_BYTES (TOPK * 32 * 4)             // 128000 B: max(scan mask 125K, sort 32K, sred 21K)

// ---------------- device scratch ----------------
__device__ unsigned int       g_scores[N_ANCH];
__device__ unsigned int       g_hist1[65536];   // zeroed by resolve1 phase each run
__device__ unsigned int       g_hist2[256];     // zeroed by block 1 at kernel start
__device__ unsigned int       g_sel_b, g_kth2;
__device__ int                g_cand_cnt;
__device__ unsigned long long g_cand[CAP];
__device__ int                g_topk_idx[TOPK];
__device__ float4             g_boxk[TOPK];
__device__ unsigned int       g_maskmat[TOPK * 32];
__device__ unsigned int       g_bar_count;      // returns to 0 after every barrier
__device__ unsigned int       g_bar_gen;        // monotonic across barriers AND replays

// ---------------- software grid barrier (monotonic generation) ----------------
__device__ __forceinline__ void gbar(unsigned int base, unsigned int k, bool wait) {
    __syncthreads();
    if (threadIdx.x == 0) {
        __threadfence();                               // publish this block's prior writes
        unsigned int a = atomicAdd(&g_bar_count, 1u) + 1u;
        if (a == GRIDB) {
            g_bar_count = 0u;
            __threadfence();
            atomicExch(&g_bar_gen, base + k);          // release generation k
        } else if (wait) {
            while (atomicAdd(&g_bar_gen, 0u) - base < k) __nanosleep(64);
            __threadfence();
        }
    }
    __syncthreads();
}

// ---------------- the single fused kernel ----------------
extern "C" __global__ void __launch_bounds__(NTHR, 1)
nms_fused_kernel(const float* __restrict__ boxes,
                 const float* __restrict__ cls,
                 const float* __restrict__ det,
                 float* __restrict__ out) {
    extern __shared__ unsigned char dynsmem[];
    __shared__ unsigned int suf[1024];
    __shared__ unsigned int win64[64];
    __shared__ int          s_win;
    __shared__ unsigned int h2s[256];
    __shared__ unsigned int sT;
    __shared__ unsigned int keepw[32];
    __shared__ unsigned int wpref[32];
    __shared__ int          s_sel[MAXBOX];
    __shared__ int          s_nkeep;
    __shared__ unsigned int s_base;

    const int t   = threadIdx.x;
    const int blk = blockIdx.x;
    const int gtid = blk * NTHR + t;

    // launch-start state: read barrier base; block 1 resets per-run scratch
    if (t == 0) s_base = atomicAdd(&g_bar_gen, 0u);
    if (blk == 1) {
        if (t < 256) g_hist2[t] = 0u;
        if (t == 0)  g_cand_cnt = 0;
    }
    __syncthreads();
    const unsigned int base = s_base;

    // ===== Phase 1: per-anchor max over 80 classes + 16-bit histogram =====
    {
        float* sred = (float*)dynsmem;                 // APT * SRED_PITCH floats
        const float4* p = (const float4*)cls;
        for (int tile = blk; tile < NTILES; tile += GRIDB) {
            int a0 = tile * APT;
            int na = min(APT, N_ANCH - a0);
            int nf4 = na * (N_CLS / 4);
            size_t gbase = (size_t)a0 * (N_CLS / 4);
            __syncthreads();                           // protect sred reuse
            for (int off = t; off < nf4; off += NTHR) {
                float4 v = p[gbase + off];
                int an = off / (N_CLS / 4);
                int c  = off % (N_CLS / 4);
                sred[an * SRED_PITCH + c] = fmaxf(fmaxf(v.x, v.y), fmaxf(v.z, v.w));
            }
            __syncthreads();
            if (t < na) {
                const float* r = &sred[t * SRED_PITCH];
                float m = r[0];
#pragma unroll
                for (int i = 1; i < N_CLS / 4; i++) m = fmaxf(m, r[i]);
                unsigned int k = __float_as_uint(m);   // scores >= 0 -> monotonic bits
                g_scores[a0 + t] = k;
                unsigned int bucket = k >> 16;
                unsigned int amask = __activemask();
                unsigned int peers = __match_any_sync(amask, bucket);
                int leader = __ffs(peers) - 1;
                if ((t & 31) == leader) atomicAdd(&g_hist1[bucket], __popc(peers));
            }
        }
    }
    gbar(base, 1, true);

    // ===== Phase 2: resolve 16-bit bucket (block 0) + zero hist1 =====
    if (blk == 0) {
        unsigned int s = 0;
        const uint4* hp = (const uint4*)g_hist1;
#pragma unroll
        for (int i = 0; i < 16; i++) {
            uint4 v = hp[t * 16 + i];
            s += v.x + v.y + v.z + v.w;
        }
        suf[t] = s;
        __syncthreads();
        for (int off = 1; off < 1024; off <<= 1) {
            unsigned int v = suf[t];
            unsigned int u = (t + off < 1024) ? suf[t + off] : 0u;
            __syncthreads();
            suf[t] = v + u;
            __syncthreads();
        }
        unsigned int excl = (t < 1023) ? suf[t + 1] : 0u;
        if (excl < TOPK && suf[t] >= TOPK) s_win = t;
        __syncthreads();
        int w = s_win;
        unsigned int wexcl = (w < 1023) ? suf[w + 1] : 0u;
        if (t < 64) win64[t] = g_hist1[w * 64 + t];
        __syncthreads();
        for (int off = 1; off < 64; off <<= 1) {
            unsigned int v = 0, u = 0;
            if (t < 64) { v = win64[t]; u = (t + off < 64) ? win64[t + off] : 0u; }
            __syncthreads();
            if (t < 64) win64[t] = v + u;
            __syncthreads();
        }
        if (t < 64) {
            unsigned int e = wexcl + ((t < 63) ? win64[t + 1] : 0u);
            unsigned int inc = wexcl + win64[t];
            if (e < TOPK && inc >= TOPK) {
                g_sel_b = (unsigned int)(w * 64 + t);
                g_kth2  = TOPK - e;
            }
        }
        __syncthreads();
        uint4 z = make_uint4(0, 0, 0, 0);
        uint4* hz = (uint4*)g_hist1;
#pragma unroll
        for (int i = 0; i < 16; i++) hz[t * 16 + i] = z;
    }
    gbar(base, 2, true);

    // ===== Phase 3: 8-bit refinement histogram (grid-wide) =====
    {
        unsigned int b = g_sel_b;
        if (gtid < N_ANCH / 4) {
            uint4 k = ((const uint4*)g_scores)[gtid];
            if ((k.x >> 16) == b) atomicAdd(&g_hist2[(k.x >> 8) & 255u], 1u);
            if ((k.y >> 16) == b) atomicAdd(&g_hist2[(k.y >> 8) & 255u], 1u);
            if ((k.z >> 16) == b) atomicAdd(&g_hist2[(k.z >> 8) & 255u], 1u);
            if ((k.w >> 16) == b) atomicAdd(&g_hist2[(k.w >> 8) & 255u], 1u);
        }
    }
    gbar(base, 3, true);

    // ===== Phase 4: per-block redundant resolve2 + grid-wide compact =====
    {
        if (t < 256) h2s[t] = g_hist2[t];
        __syncthreads();
        for (int off = 1; off < 256; off <<= 1) {
            unsigned int v = 0, u = 0;
            if (t < 256) { v = h2s[t]; u = (t + off < 256) ? h2s[t + off] : 0u; }
            __syncthreads();
            if (t < 256) h2s[t] = v + u;
            __syncthreads();
        }
        if (t < 256) {
            unsigned int kth = g_kth2;
            unsigned int e = (t < 255) ? h2s[t + 1] : 0u;
            if (e < kth && h2s[t] >= kth)
                sT = (g_sel_b << 16) | ((unsigned int)t << 8);
        }
        __syncthreads();
        unsigned int T = sT;
        if (gtid < N_ANCH / 4) {
            uint4 k = ((const uint4*)g_scores)[gtid];
            unsigned int bi = (unsigned int)(gtid * 4);
            if (k.x >= T) { int s = atomicAdd(&g_cand_cnt, 1); if (s < CAP) g_cand[s] = ((unsigned long long)k.x << 32) | (0xFFFFFFFFu - bi); }
            if (k.y >= T) { int s = atomicAdd(&g_cand_cnt, 1); if (s < CAP) g_cand[s] = ((unsigned long long)k.y << 32) | (0xFFFFFFFFu - (bi + 1)); }
            if (k.z >= T) { int s = atomicAdd(&g_cand_cnt, 1); if (s < CAP) g_cand[s] = ((unsigned long long)k.z << 32) | (0xFFFFFFFFu - (bi + 2)); }
            if (k.w >= T) { int s = atomicAdd(&g_cand_cnt, 1); if (s < CAP) g_cand[s] = ((unsigned long long)k.w << 32) | (0xFFFFFFFFu - (bi + 3)); }
        }
    }
    gbar(base, 4, true);

    // ===== Phase 5: bitonic sort of candidates + box gather (block 0) =====
    if (blk == 0) {
        unsigned long long* scand = (unsigned long long*)dynsmem;
        int cnt = g_cand_cnt;
        if (cnt > CAP) cnt = CAP;
        int S = (cnt <= 2048) ? 2048 : CAP;
        for (int i = t; i < S; i += NTHR)
            scand[i] = (i < cnt) ? g_cand[i] : 0ull;
        __syncthreads();
        for (int k = 2; k <= S; k <<= 1) {
            for (int j = k >> 1; j > 0; j >>= 1) {
                for (int idx = t; idx < S; idx += NTHR) {
                    int l = idx ^ j;
                    if (l > idx) {
                        bool up = ((idx & k) == 0);
                        unsigned long long a = scand[idx], b = scand[l];
                        bool sw = up ? (a < b) : (a > b);
                        if (sw) { scand[idx] = b; scand[l] = a; }
                    }
                }
                __syncthreads();
            }
        }
        if (t < TOPK) {
            unsigned long long key = scand[t];
            int idx = (int)(0xFFFFFFFFu - (unsigned int)key);
            g_topk_idx[t] = idx;
            g_boxk[t] = ((const float4*)boxes)[idx];
        }
    }
    gbar(base, 5, true);

    // ===== Phase 6: IoU > thr bitmask (grid-wide, bit-exact fp32) =====
    {
        int w = gtid;
        if (w < TOPK * 32) {
            int i = w >> 5, wj = w & 31;
            float4 bi = g_boxk[i];
            float ai = __fmul_rn(__fsub_rn(bi.z, bi.x), __fsub_rn(bi.w, bi.y));
            unsigned int bits = 0u;
            int j0 = wj * 32;
#pragma unroll 8
            for (int tt = 0; tt < 32; tt++) {
                int j = j0 + tt;
                if (j < TOPK) {
                    float4 bj = g_boxk[j];
                    float aj = __fmul_rn(__fsub_rn(bj.z, bj.x), __fsub_rn(bj.w, bj.y));
                    float ih = fmaxf(__fsub_rn(fminf(bi.z, bj.z), fmaxf(bi.x, bj.x)), 0.0f);
                    float iw = fmaxf(__fsub_rn(fminf(bi.w, bj.w), fmaxf(bi.y, bj.y)), 0.0f);
                    float inter = __fmul_rn(ih, iw);
                    float denom = __fadd_rn(__fsub_rn(__fadd_rn(ai, aj), inter), 1e-8f);
                    float iou = __fdiv_rn(inter, denom);
                    if (iou > NMS_THR) bits |= (1u << tt);
                }
            }
            g_maskmat[w] = bits;
        }
    }
    // blocks != 0 arrive and exit; block 0 waits then finishes
    gbar(base, 6, blk == 0);
    if (blk != 0) return;

    // ===== Phase 7: sequential greedy keep-scan + output gather (block 0) =====
    {
        unsigned int* smask = (unsigned int*)dynsmem;   // TOPK*32 words
        for (int i = t; i < TOPK * 32; i += NTHR) smask[i] = g_maskmat[i];
        __syncthreads();

        if (t < 32) {
            unsigned int kw = 0u;
            unsigned int m = smask[t];                  // prefetch row 0
            for (int i = 0; i < TOPK; i++) {
                unsigned int mn = (i + 1 < TOPK) ? smask[(i + 1) * 32 + t] : 0u;
                int any = __any_sync(0xFFFFFFFFu, (kw & m) != 0u);
                if (!any && t == (i >> 5)) kw |= 1u << (i & 31);
                m = mn;
            }
            keepw[t] = kw;
            unsigned int pc = __popc(kw);
            unsigned int inc = pc;
            for (int off = 1; off < 32; off <<= 1) {
                unsigned int v = __shfl_up_sync(0xFFFFFFFFu, inc, off);
                if (t >= off) inc += v;
            }
            wpref[t] = inc - pc;
            if (t == 31) s_nkeep = (int)inc;
        }
        __syncthreads();

        if (t < TOPK) {
            int w = t >> 5, b = t & 31;
            unsigned int kw = keepw[w];
            if ((kw >> b) & 1u) {
                int rank = (int)wpref[w] + __popc(kw & ((1u << b) - 1u));
                if (rank < MAXBOX) s_sel[rank] = g_topk_idx[t];
            }
        }
        __syncthreads();

        int nk = s_nkeep;
        if (nk > MAXBOX) nk = MAXBOX;
        for (int e = t; e < MAXBOX * DET_DIM; e += NTHR) {
            int r = e / DET_DIM;
            int c = e - r * DET_DIM;
            out[e] = (r < nk) ? det[(size_t)s_sel[r] * DET_DIM + c] : 0.0f;
        }
    }
}

// ---------------- launch: ONE kernel ----------------
extern "C" void kernel_launch(void* const* d_in, const int* in_sizes, int n_in,
                              void* d_out, int out_size) {
    const float* boxes = (const float*)d_in[0];
    const float* cls   = (const float*)d_in[1];
    const float* det   = (const float*)d_in[2];
    float* out = (float*)d_out;

    cudaFuncSetAttribute((const void*)nms_fused_kernel,
                         cudaFuncAttributeMaxDynamicSharedMemorySize, DYN_BYTES);

    nms_fused_kernel<<<GRIDB, NTHR, DYN_BYTES>>>(boxes, cls, det, out);
}